// round 13
// baseline (speedup 1.0000x reference)
#include <cuda_runtime.h>
#include <cuda_bf16.h>
#include <cstdint>

// CumulativeNormalizer: x [32, 512, 4000] fp32.
// out[b,f,t] = (x[t] - mean(x[0..t])) / sqrt(var(x[0..t]) + 1e-4)
//
// One 128-thread block per row, row processed in TWO 2000-frame halves
// through a single 9KB smem buffer with (S,Q) carried across halves.
// 16 resident blocks/SM (64 warps, 100% theoretical occupancy) give dense
// cross-block load/compute phase interleaving. Per half: cp.async stage
// (padded, conflict-free), thread-local 16-elem totals + warp scan +
// 4-warp combine (+carry), epilogue in place, coalesced streaming store.
// Identity: out = (x*c - S) * rsqrt(c*Q - S^2 + eps*c^2)  -> 1 MUFU/elem.

#define FRAMES  4000
#define ROWS    (32 * 512)
#define EPS     1e-4f
#define THREADS 128
#define HALF    2000
#define SEG     16
#define ACTIVE  125                          // 125 * 16 = 2000
#define VEC4H   (HALF / 4)                   // 500 float4 per half
#define PADDEDH (HALF + 4 * (HALF / 32))     // 2250 floats = 9000 B
#define NWARPS  4

__device__ __forceinline__ int padi(int i) { return i + ((i >> 5) << 2); }

__global__ __launch_bounds__(THREADS, 16)
void cumnorm_kernel(const float* __restrict__ x, float* __restrict__ out) {
    __shared__ float sd[PADDEDH];
    __shared__ float swS[NWARPS];
    __shared__ float swQ[NWARPS];

    const int tid  = threadIdx.x;
    const int lane = tid & 31;
    const int w    = tid >> 5;
    const int row  = blockIdx.x;

    const unsigned sbase = (unsigned)__cvta_generic_to_shared(sd);
    const unsigned FULL  = 0xFFFFFFFFu;

    float carryS = 0.f, carryQ = 0.f;

    #pragma unroll
    for (int h = 0; h < 2; h++) {
        const float* __restrict__ xr = x   + (size_t)row * FRAMES + h * HALF;
        float*       __restrict__ yr = out + (size_t)row * FRAMES + h * HALF;

        // ---- Stage half -> shared (cp.async.cg, coalesced, padded dst) ----
        #pragma unroll
        for (int k = 0; k < 4; k++) {
            const int i4 = tid + THREADS * k;
            if (i4 < VEC4H) {
                const int g = i4 * 4;
                const unsigned dst = sbase + (unsigned)(padi(g) * 4);
                asm volatile("cp.async.cg.shared.global [%0], [%1], 16;\n"
                             :: "r"(dst), "l"(xr + g));
            }
        }
        asm volatile("cp.async.commit_group;\n");
        asm volatile("cp.async.wait_group 0;\n");
        __syncthreads();

        // ---- Per-thread segment totals over 16 contiguous frames ----
        float S = 0.f, Q = 0.f;
        if (tid < ACTIVE) {
            const int p0 = padi(tid * SEG);   // contiguous in padded space
            #pragma unroll
            for (int j = 0; j < 4; j++) {
                const float4 v = *reinterpret_cast<const float4*>(&sd[p0 + 4 * j]);
                S += v.x + v.y + v.z + v.w;
                Q = fmaf(v.x, v.x, Q);
                Q = fmaf(v.y, v.y, Q);
                Q = fmaf(v.z, v.z, Q);
                Q = fmaf(v.w, v.w, Q);
            }
        }

        // ---- Warp inclusive scan over segment totals ----
        float is = S, iq = Q;
        #pragma unroll
        for (int off = 1; off < 32; off <<= 1) {
            const float ts = __shfl_up_sync(FULL, is, off);
            const float tq = __shfl_up_sync(FULL, iq, off);
            if (lane >= off) { is += ts; iq += tq; }
        }
        if (lane == 31) { swS[w] = is; swQ[w] = iq; }
        __syncthreads();

        // ---- Cross-warp exclusive offset + half totals (broadcast reads) ----
        float offS = 0.f, offQ = 0.f, totS = 0.f, totQ = 0.f;
        #pragma unroll
        for (int ww = 0; ww < NWARPS; ww++) {
            const float a = swS[ww], b = swQ[ww];
            if (ww < w) { offS += a; offQ += b; }
            totS += a; totQ += b;
        }
        const float baseS = carryS + offS + (is - S);
        const float baseQ = carryQ + offQ + (iq - Q);
        carryS += totS;
        carryQ += totQ;

        // ---- Epilogue: accumulate inside segment, normalize in place ----
        if (tid < ACTIVE) {
            const int p0 = padi(tid * SEG);
            float s = baseS, q = baseQ;
            float c = (float)(h * HALF + tid * SEG + 1);
            #pragma unroll
            for (int j = 0; j < 4; j++) {
                const float4 v = *reinterpret_cast<const float4*>(&sd[p0 + 4 * j]);
                float4 o;
                {   s += v.x; q = fmaf(v.x, v.x, q);
                    float t = fmaf(c, q, -s * s); t = fmaf(EPS * c, c, t);
                    o.x = fmaf(v.x, c, -s) * rsqrtf(t); c += 1.0f; }
                {   s += v.y; q = fmaf(v.y, v.y, q);
                    float t = fmaf(c, q, -s * s); t = fmaf(EPS * c, c, t);
                    o.y = fmaf(v.y, c, -s) * rsqrtf(t); c += 1.0f; }
                {   s += v.z; q = fmaf(v.z, v.z, q);
                    float t = fmaf(c, q, -s * s); t = fmaf(EPS * c, c, t);
                    o.z = fmaf(v.z, c, -s) * rsqrtf(t); c += 1.0f; }
                {   s += v.w; q = fmaf(v.w, v.w, q);
                    float t = fmaf(c, q, -s * s); t = fmaf(EPS * c, c, t);
                    o.w = fmaf(v.w, c, -s) * rsqrtf(t); c += 1.0f; }
                *reinterpret_cast<float4*>(&sd[p0 + 4 * j]) = o;   // own slots
            }
        }
        __syncthreads();

        // ---- Unstage: shared -> global, coalesced streaming stores ----
        #pragma unroll
        for (int k = 0; k < 4; k++) {
            const int i4 = tid + THREADS * k;
            if (i4 < VEC4H) {
                const int g = i4 * 4;
                const float4 v = *reinterpret_cast<const float4*>(&sd[padi(g)]);
                __stcs(reinterpret_cast<float4*>(yr + g), v);
            }
        }

        // Before next half's cp.async overwrites sd, all reads must be done.
        if (h == 0) __syncthreads();
    }
}

extern "C" void kernel_launch(void* const* d_in, const int* in_sizes, int n_in,
                              void* d_out, int out_size) {
    const float* x = (const float*)d_in[0];
    float* out = (float*)d_out;
    (void)in_sizes; (void)n_in; (void)out_size;

    cumnorm_kernel<<<ROWS, THREADS>>>(x, out);   // one block per row
}

// round 14
// speedup vs baseline: 1.0508x; 1.0508x over previous
#include <cuda_runtime.h>
#include <cuda_bf16.h>
#include <cstdint>

// CumulativeNormalizer: x [32, 512, 4000] fp32.
// out[b,f,t] = (x[t] - mean(x[0..t])) / sqrt(var(x[0..t]) + 1e-4)
//
// One 128-thread block per row (R11 structure, best so far). Instead of
// +4-float-per-32 padding, a float4-granularity XOR swizzle
// (sw4(i) = i ^ ((i>>3)&7)) makes all LDS/STS phases conflict-free with
// ZERO smem overhead: exactly 16000 B/block -> 14 resident blocks/SM
// (vs 12), denser cross-block load/compute phase interleaving.
// Per row: cp.async stage, thread-local 32-elem totals + warp scan +
// 4-warp combine, epilogue in place, coalesced streaming store.
// Identity: out = (x*c - S) * rsqrt(c*Q - S^2 + eps*c^2)  -> 1 MUFU/elem.

#define FRAMES  4000
#define ROWS    (32 * 512)
#define EPS     1e-4f
#define THREADS 128
#define SEG     32
#define ACTIVE  125                  // 125 * 32 = 4000
#define VEC4    (FRAMES / 4)         // 1000 float4 per row
#define NWARPS  4

// Swizzle in float4 units: XOR the 16B-bank column with bits [5:3].
__device__ __forceinline__ int swz4(int i4) { return i4 ^ ((i4 >> 3) & 7); }

__global__ __launch_bounds__(THREADS, 14)
void cumnorm_kernel(const float* __restrict__ x, float* __restrict__ out) {
    __shared__ float4 sd[VEC4];      // 16000 B exactly
    __shared__ float swS[NWARPS];
    __shared__ float swQ[NWARPS];

    const int tid  = threadIdx.x;
    const int lane = tid & 31;
    const int w    = tid >> 5;
    const int row  = blockIdx.x;

    const float* __restrict__ xr = x   + (size_t)row * FRAMES;
    float*       __restrict__ yr = out + (size_t)row * FRAMES;

    // ---- Stage row -> shared (cp.async.cg, coalesced, swizzled dst) ----
    const unsigned sbase = (unsigned)__cvta_generic_to_shared(sd);
    #pragma unroll
    for (int k = 0; k < 8; k++) {
        const int i4 = tid + THREADS * k;
        if (i4 < VEC4) {
            const unsigned dst = sbase + (unsigned)(swz4(i4) * 16);
            asm volatile("cp.async.cg.shared.global [%0], [%1], 16;\n"
                         :: "r"(dst), "l"(xr + i4 * 4));
        }
    }
    asm volatile("cp.async.commit_group;\n");
    asm volatile("cp.async.wait_group 0;\n");
    __syncthreads();

    // ---- Per-thread segment totals (S,Q) over 32 contiguous frames ----
    float S = 0.f, Q = 0.f;
    if (tid < ACTIVE) {
        const int s4 = tid * 8;          // first float4 of this segment
        #pragma unroll
        for (int j = 0; j < 8; j++) {
            const float4 v = sd[swz4(s4 + j)];
            S += v.x + v.y + v.z + v.w;
            Q = fmaf(v.x, v.x, Q);
            Q = fmaf(v.y, v.y, Q);
            Q = fmaf(v.z, v.z, Q);
            Q = fmaf(v.w, v.w, Q);
        }
    }

    // ---- Warp inclusive scan over segment totals ----
    const unsigned FULL = 0xFFFFFFFFu;
    float is = S, iq = Q;
    #pragma unroll
    for (int off = 1; off < 32; off <<= 1) {
        const float ts = __shfl_up_sync(FULL, is, off);
        const float tq = __shfl_up_sync(FULL, iq, off);
        if (lane >= off) { is += ts; iq += tq; }
    }
    if (lane == 31) { swS[w] = is; swQ[w] = iq; }
    __syncthreads();

    // ---- Cross-warp exclusive offset (4 warps, broadcast reads) ----
    float offS = 0.f, offQ = 0.f;
    #pragma unroll
    for (int ww = 0; ww < NWARPS - 1; ww++) {
        if (ww < w) { offS += swS[ww]; offQ += swQ[ww]; }
    }
    const float baseS = offS + (is - S);   // exclusive prefix before segment
    const float baseQ = offQ + (iq - Q);

    // ---- Epilogue: accumulate inside segment, normalize in place ----
    if (tid < ACTIVE) {
        const int s4 = tid * 8;
        float s = baseS, q = baseQ;
        float c = (float)(tid * SEG + 1);
        #pragma unroll
        for (int j = 0; j < 8; j++) {
            const int p = swz4(s4 + j);
            const float4 v = sd[p];
            float4 o;
            {   s += v.x; q = fmaf(v.x, v.x, q);
                float t = fmaf(c, q, -s * s); t = fmaf(EPS * c, c, t);
                o.x = fmaf(v.x, c, -s) * rsqrtf(t); c += 1.0f; }
            {   s += v.y; q = fmaf(v.y, v.y, q);
                float t = fmaf(c, q, -s * s); t = fmaf(EPS * c, c, t);
                o.y = fmaf(v.y, c, -s) * rsqrtf(t); c += 1.0f; }
            {   s += v.z; q = fmaf(v.z, v.z, q);
                float t = fmaf(c, q, -s * s); t = fmaf(EPS * c, c, t);
                o.z = fmaf(v.z, c, -s) * rsqrtf(t); c += 1.0f; }
            {   s += v.w; q = fmaf(v.w, v.w, q);
                float t = fmaf(c, q, -s * s); t = fmaf(EPS * c, c, t);
                o.w = fmaf(v.w, c, -s) * rsqrtf(t); c += 1.0f; }
            sd[p] = o;                      // own slots only
        }
    }
    __syncthreads();

    // ---- Unstage: shared -> global, coalesced streaming stores ----
    #pragma unroll
    for (int k = 0; k < 8; k++) {
        const int i4 = tid + THREADS * k;
        if (i4 < VEC4) {
            const float4 v = sd[swz4(i4)];
            __stcs(reinterpret_cast<float4*>(yr + i4 * 4), v);
        }
    }
}

extern "C" void kernel_launch(void* const* d_in, const int* in_sizes, int n_in,
                              void* d_out, int out_size) {
    const float* x = (const float*)d_in[0];
    float* out = (float*)d_out;
    (void)in_sizes; (void)n_in; (void)out_size;

    cumnorm_kernel<<<ROWS, THREADS>>>(x, out);   // one block per row
}